// round 13
// baseline (speedup 1.0000x reference)
#include <cuda_runtime.h>
#include <cuda_fp16.h>
#include <cstdint>
#include <math.h>

#define BH   32
#define SEQ  2048
#define HD   64
#define BM   128
#define BN   64
#define NTHR 256
#define LOG2E 1.4426950408889634f

#define RB   144                       // smem row bytes (128 data + 16 pad)
#define QHI_OFF 0
#define STG_OFF 18432                  // two 18432B stages follow
#define STG_SZ  18432
// within a stage: KHI +0, VTHI +9216
#define RED_OFF (STG_OFF + 2 * STG_SZ) // 55296
#define SMEM_TOTAL (RED_OFF + 256)     // 55552 -> 4 CTAs/SM fits 222KB

// pre-converted operands (written by prep_kernel each launch)
__device__ __half g_khi[(size_t)BH * SEQ * HD];
__device__ __half g_vthi[(size_t)BH * HD * SEQ];   // [bh][d][n]

__device__ __forceinline__ void atomic_max_pos(float* addr, float v) {
    atomicMax(reinterpret_cast<unsigned int*>(addr), __float_as_uint(v));
}
__device__ __forceinline__ uint32_t smem_u32(const void* p) {
    uint32_t a;
    asm("{ .reg .u64 t; cvta.to.shared.u64 t, %1; cvt.u32.u64 %0, t; }" : "=r"(a) : "l"(p));
    return a;
}
__device__ __forceinline__ void ldsm4(uint32_t r[4], uint32_t addr) {
    asm volatile("ldmatrix.sync.aligned.m8n8.x4.shared.b16 {%0,%1,%2,%3}, [%4];"
                 : "=r"(r[0]), "=r"(r[1]), "=r"(r[2]), "=r"(r[3]) : "r"(addr));
}
__device__ __forceinline__ void mma16816(float d[4], const uint32_t a[4],
                                         uint32_t b0, uint32_t b1) {
    asm volatile("mma.sync.aligned.m16n8k16.row.col.f32.f16.f16.f32 "
                 "{%0,%1,%2,%3},{%4,%5,%6,%7},{%8,%9},{%0,%1,%2,%3};"
                 : "+f"(d[0]), "+f"(d[1]), "+f"(d[2]), "+f"(d[3])
                 : "r"(a[0]), "r"(a[1]), "r"(a[2]), "r"(a[3]), "r"(b0), "r"(b1));
}
__device__ __forceinline__ uint32_t packhf(float x, float y) {
    __half2 h = __float22half2_rn(make_float2(x, y));
    return *reinterpret_cast<uint32_t*>(&h);
}
__device__ __forceinline__ uint32_t hmax2u(uint32_t a, uint32_t b) {
    __half2 r = __hmax2(*reinterpret_cast<__half2*>(&a), *reinterpret_cast<__half2*>(&b));
    return *reinterpret_cast<uint32_t*>(&r);
}
__device__ __forceinline__ float hmax2_to_f(uint32_t u) {
    float2 f = __half22float2(*reinterpret_cast<__half2*>(&u));
    return fmaxf(f.x, f.y);
}
__device__ __forceinline__ float ex2(float x) {
    float r; asm("ex2.approx.f32 %0, %1;" : "=f"(r) : "f"(x)); return r;
}
__device__ __forceinline__ void cpasync16(uint32_t dst, const void* src) {
    asm volatile("cp.async.cg.shared.global [%0], [%1], 16;" :: "r"(dst), "l"(src) : "memory");
}
#define CP_COMMIT() asm volatile("cp.async.commit_group;" ::: "memory")
#define CP_WAIT0()  asm volatile("cp.async.wait_group 0;" ::: "memory")

// ---- pre-pass: K -> fp16, V -> V^T fp16; also zero the amax tail ----
__global__ __launch_bounds__(256) void prep_kernel(const float* __restrict__ k,
                                                   const float* __restrict__ v,
                                                   float* __restrict__ tail) {
    __shared__ float vs[64][65];
    const int n0 = blockIdx.x * 64;
    const int bh = blockIdx.y;
    const int t = threadIdx.x;
    if (blockIdx.x == 0 && blockIdx.y == 0 && t == 0) { tail[0] = 0.0f; tail[1] = 0.0f; }
    const size_t base = (size_t)bh * SEQ * HD;

    for (int i = t; i < 64 * 16; i += 256) {
        int r = i >> 4, c = (i & 15) * 4;
        size_t eo = base + (size_t)(n0 + r) * HD + c;
        float4 kk = *(const float4*)(k + eo);
        *(uint2*)((uint16_t*)g_khi + eo) =
            make_uint2(packhf(kk.x, kk.y), packhf(kk.z, kk.w));
        float4 vv = *(const float4*)(v + eo);
        vs[r][c] = vv.x; vs[r][c + 1] = vv.y; vs[r][c + 2] = vv.z; vs[r][c + 3] = vv.w;
    }
    __syncthreads();
    const int d = t >> 2;
    const int nn0 = (t & 3) * 16;
    const size_t vbase = ((size_t)bh * HD + d) * SEQ + n0;
    #pragma unroll
    for (int nb = 0; nb < 4; nb++) {
        int n = nn0 + nb * 4;
        *(uint2*)((uint16_t*)g_vthi + vbase + n) =
            make_uint2(packhf(vs[n][d], vs[n + 1][d]), packhf(vs[n + 2][d], vs[n + 3][d]));
    }
}

// async-load one 64-row K/V^T tile (fp16, pre-converted) into a smem stage
__device__ __forceinline__ void issue_tile(uint32_t stg, int bh, int n0, int t) {
    const char* skhi = (const char*)g_khi + ((size_t)bh * SEQ + n0) * HD * 2;
    const char* svhi = (const char*)g_vthi + ((size_t)bh * HD * SEQ + n0) * 2;
    #pragma unroll
    for (int j = 0; j < 2; j++) {
        int rid = (j << 8) + t;            // 0..511 chunks per region
        int r = rid >> 3, c16 = rid & 7;
        cpasync16(stg + r * RB + c16 * 16, skhi + rid * 16);               // K rows 128B
        cpasync16(stg + 9216 + r * RB + c16 * 16,
                  svhi + (size_t)r * (SEQ * 2) + c16 * 16);                // V^T stride 4KB
    }
}

__global__ __launch_bounds__(NTHR, 4) void fa_mma_kernel(
    const float* __restrict__ q,
    const float* __restrict__ dsq, const float* __restrict__ dsk, const float* __restrict__ dsv,
    const float* __restrict__ qss, const float* __restrict__ qso, const float* __restrict__ dss,
    float* __restrict__ out, float* __restrict__ amax_tail)
{
    extern __shared__ char smem[];
    const uint32_t sb = smem_u32(smem);
    float* redf = (float*)(smem + RED_OFF);

    const int t = threadIdx.x, w = t >> 5, lane = t & 31;
    const int g = lane >> 2, tig = lane & 3;
    const int subm = lane >> 3;
    const int a_r = (lane & 7) + ((subm & 1) << 3);
    const int a_c = ((subm >> 1) << 3);
    const int b_r = (lane & 7) + ((subm >> 1) << 3);
    const int b_c = ((subm & 1) << 3);

    const int qt = (gridDim.x - 1) - blockIdx.x;          // heavy tiles first
    const int bh = blockIdx.y;
    const size_t base = (size_t)bh * SEQ * HD;
    const int q0 = qt * BM;

    const float qk_scale = dsq[0] * dsk[0] * 0.125f * LOG2E;   // ex2 domain
    const float pv_scale = qss[0] * dss[0] * dsv[0];
    const float o_scale  = qso[0];

    // prefetch tile 0 first, then convert Q
    issue_tile(sb + STG_OFF, bh, 0, t);
    CP_COMMIT();

    for (int i = t; i < BM * (HD / 4); i += NTHR) {
        int r = i >> 4, c = (i & 15) * 4;
        float4 val = *(const float4*)(q + base + (size_t)(q0 + r) * HD + c);
        val.x *= qk_scale; val.y *= qk_scale; val.z *= qk_scale; val.w *= qk_scale;
        *(uint2*)(smem + QHI_OFF + r * RB + c * 2) =
            make_uint2(packhf(val.x, val.y), packhf(val.z, val.w));
    }

    float o_acc[8][4];
    #pragma unroll
    for (int nb = 0; nb < 8; nb++)
        #pragma unroll
        for (int j = 0; j < 4; j++) o_acc[nb][j] = 0.0f;
    float l0 = 0.0f, l1 = 0.0f;                 // row sums (f32, per-thread partial)
    uint32_t hm0 = 0u, hm1 = 0u;                // running fp16x2 max p per row

    const int row_w = q0 + w * 16;
    const int row_hi = row_w + 15;
    const int n_tiles = 2 * qt + 2;

    for (int kt = 0; kt < n_tiles; kt++) {
        const int n0 = kt * BN;
        CP_WAIT0();
        __syncthreads();
        if (kt + 1 < n_tiles) {
            issue_tile(sb + STG_OFF + ((kt + 1) & 1) * STG_SZ, bh, n0 + BN, t);
            CP_COMMIT();
        }
        const uint32_t stg = sb + STG_OFF + (kt & 1) * STG_SZ;

        if (n0 > row_hi) continue;

        #pragma unroll
        for (int h = 0; h < 2; h++) {            // 32-col half-passes
            const int c_base = n0 + h * 32;
            if (c_base > row_hi) break;          // upper half fully masked

            // ---- S = Q K^T on this half (single-pass fp16) ----
            float s[4][4];
            #pragma unroll
            for (int j = 0; j < 4; j++)
                #pragma unroll
                for (int d = 0; d < 4; d++) s[j][d] = 0.0f;

            #pragma unroll
            for (int kb = 0; kb < 4; kb++) {
                uint32_t ah[4], b[4];
                ldsm4(ah, sb + QHI_OFF +
                      (uint32_t)((w * 16 + a_r) * RB + (kb * 16 + a_c) * 2));
                #pragma unroll
                for (int np2 = 0; np2 < 2; np2++) {
                    ldsm4(b, stg + (uint32_t)(((h * 2 + np2) * 16 + b_r) * RB +
                                              (kb * 16 + b_c) * 2));
                    mma16816(s[np2 * 2],     ah, b[0], b[1]);
                    mma16816(s[np2 * 2 + 1], ah, b[2], b[3]);
                }
            }

            // ---- causal mask (half-local) ----
            if (c_base + 31 > row_w) {
                const int r0g = row_w + g, r1g = r0g + 8;
                #pragma unroll
                for (int nb = 0; nb < 4; nb++) {
                    const int c0 = c_base + nb * 8 + tig * 2;
                    if (c0 > r0g)     s[nb][0] = -1e30f;
                    if (c0 + 1 > r0g) s[nb][1] = -1e30f;
                    if (c0 > r1g)     s[nb][2] = -1e30f;
                    if (c0 + 1 > r1g) s[nb][3] = -1e30f;
                }
            }

            // ---- p = 2^s, accumulate l, pack, fp16 max ----
            uint32_t ph[8];
            #pragma unroll
            for (int nb = 0; nb < 4; nb++) {
                float p0 = ex2(s[nb][0]);
                float p1 = ex2(s[nb][1]);
                float p2 = ex2(s[nb][2]);
                float p3 = ex2(s[nb][3]);
                l0 += p0 + p1;
                l1 += p2 + p3;
                ph[nb * 2]     = packhf(p0, p1);
                ph[nb * 2 + 1] = packhf(p2, p3);
                hm0 = hmax2u(hm0, ph[nb * 2]);
                hm1 = hmax2u(hm1, ph[nb * 2 + 1]);
            }

            // ---- O += P V on this half ----
            #pragma unroll
            for (int kb2 = 0; kb2 < 2; kb2++) {
                const uint32_t* ap = ph + kb2 * 4;
                uint32_t b[4];
                #pragma unroll
                for (int np = 0; np < 4; np++) {
                    ldsm4(b, stg + 9216 +
                          (uint32_t)((np * 16 + b_r) * RB +
                                     ((h * 2 + kb2) * 16 + b_c) * 2));
                    mma16816(o_acc[2 * np],     ap, b[0], b[1]);
                    mma16816(o_acc[2 * np + 1], ap, b[2], b[3]);
                }
            }
        }
    }

    // ---- epilogue: quad-reduce l (cols live across 4 lanes), then scale/store ----
    l0 += __shfl_xor_sync(0xffffffffu, l0, 1);
    l0 += __shfl_xor_sync(0xffffffffu, l0, 2);
    l1 += __shfl_xor_sync(0xffffffffu, l1, 1);
    l1 += __shfl_xor_sync(0xffffffffu, l1, 2);
    const float il0 = 1.0f / l0, il1 = 1.0f / l1;

    float mx0 = hmax2_to_f(hm0), mx1 = hmax2_to_f(hm1);
    float r0 = fmaxf(mx0, __shfl_xor_sync(0xffffffffu, mx0, 1));
    r0 = fmaxf(r0, __shfl_xor_sync(0xffffffffu, r0, 2));
    float r1 = fmaxf(mx1, __shfl_xor_sync(0xffffffffu, mx1, 1));
    r1 = fmaxf(r1, __shfl_xor_sync(0xffffffffu, r1, 2));
    float amax_s_loc = fmaxf(r0 * il0, r1 * il1);

    float amax_o_loc = 0.0f;
    const int r0g = row_w + g, r1g = r0g + 8;
    #pragma unroll
    for (int nb = 0; nb < 8; nb++) {
        float v0 = o_acc[nb][0] * il0 * pv_scale;
        float v1 = o_acc[nb][1] * il0 * pv_scale;
        float v2 = o_acc[nb][2] * il1 * pv_scale;
        float v3 = o_acc[nb][3] * il1 * pv_scale;
        amax_o_loc = fmaxf(amax_o_loc, fmaxf(fmaxf(fabsf(v0), fabsf(v1)),
                                             fmaxf(fabsf(v2), fabsf(v3))));
        const int c = nb * 8 + tig * 2;
        *(float2*)(out + base + (size_t)r0g * HD + c) = make_float2(v0 * o_scale, v1 * o_scale);
        *(float2*)(out + base + (size_t)r1g * HD + c) = make_float2(v2 * o_scale, v3 * o_scale);
    }

    #pragma unroll
    for (int msk = 16; msk >= 1; msk >>= 1) {
        amax_s_loc = fmaxf(amax_s_loc, __shfl_xor_sync(0xffffffffu, amax_s_loc, msk));
        amax_o_loc = fmaxf(amax_o_loc, __shfl_xor_sync(0xffffffffu, amax_o_loc, msk));
    }
    if (lane == 0) { redf[w] = amax_s_loc; redf[8 + w] = amax_o_loc; }
    __syncthreads();
    if (t == 0) {
        float as = redf[0], ao = redf[8];
        #pragma unroll
        for (int i = 1; i < 8; i++) { as = fmaxf(as, redf[i]); ao = fmaxf(ao, redf[8 + i]); }
        atomic_max_pos(&amax_tail[0], as);
        atomic_max_pos(&amax_tail[1], ao);
    }
}

extern "C" void kernel_launch(void* const* d_in, const int* in_sizes, int n_in,
                              void* d_out, int out_size) {
    const float* q   = (const float*)d_in[0];
    const float* k   = (const float*)d_in[1];
    const float* v   = (const float*)d_in[2];
    const float* dsq = (const float*)d_in[3];
    const float* dsk = (const float*)d_in[4];
    const float* dsv = (const float*)d_in[5];
    const float* qss = (const float*)d_in[6];
    const float* qso = (const float*)d_in[7];
    const float* dss = (const float*)d_in[8];
    float* out = (float*)d_out;
    float* tail = out + (out_size - 2);

    cudaFuncSetAttribute(fa_mma_kernel,
                         cudaFuncAttributeMaxDynamicSharedMemorySize, SMEM_TOTAL);

    prep_kernel<<<dim3(SEQ / 64, BH), 256>>>(k, v, tail);

    dim3 grid(SEQ / BM, BH);                 // (16, 32)
    fa_mma_kernel<<<grid, NTHR, SMEM_TOTAL>>>(q, dsq, dsk, dsv, qss, qso, dss,
                                              out, tail);
}

// round 14
// speedup vs baseline: 1.3718x; 1.3718x over previous
#include <cuda_runtime.h>
#include <cuda_fp16.h>
#include <cstdint>
#include <math.h>

#define BH   32
#define SEQ  2048
#define HD   64
#define BM   128
#define BN   64
#define NTHR 256
#define LOG2E 1.4426950408889634f

#define RB   144                       // smem row bytes (128 data + 16 pad)
#define QHI_OFF 0
#define STG_OFF 18432                  // two 18432B stages follow
#define STG_SZ  18432
// within a stage: KHI +0, VTHI +9216
#define RED_OFF (STG_OFF + 2 * STG_SZ) // 55296
#define SMEM_TOTAL (RED_OFF + 256)

// pre-converted operands (written by prep_kernel each launch)
__device__ __half g_khi[(size_t)BH * SEQ * HD];
__device__ __half g_vthi[(size_t)BH * HD * SEQ];   // [bh][d][n]

__device__ __forceinline__ void atomic_max_pos(float* addr, float v) {
    atomicMax(reinterpret_cast<unsigned int*>(addr), __float_as_uint(v));
}
__device__ __forceinline__ uint32_t smem_u32(const void* p) {
    uint32_t a;
    asm("{ .reg .u64 t; cvta.to.shared.u64 t, %1; cvt.u32.u64 %0, t; }" : "=r"(a) : "l"(p));
    return a;
}
__device__ __forceinline__ void ldsm4(uint32_t r[4], uint32_t addr) {
    asm volatile("ldmatrix.sync.aligned.m8n8.x4.shared.b16 {%0,%1,%2,%3}, [%4];"
                 : "=r"(r[0]), "=r"(r[1]), "=r"(r[2]), "=r"(r[3]) : "r"(addr));
}
__device__ __forceinline__ void mma16816(float d[4], const uint32_t a[4],
                                         uint32_t b0, uint32_t b1) {
    asm volatile("mma.sync.aligned.m16n8k16.row.col.f32.f16.f16.f32 "
                 "{%0,%1,%2,%3},{%4,%5,%6,%7},{%8,%9},{%0,%1,%2,%3};"
                 : "+f"(d[0]), "+f"(d[1]), "+f"(d[2]), "+f"(d[3])
                 : "r"(a[0]), "r"(a[1]), "r"(a[2]), "r"(a[3]), "r"(b0), "r"(b1));
}
__device__ __forceinline__ uint32_t packhf(float x, float y) {
    __half2 h = __float22half2_rn(make_float2(x, y));
    return *reinterpret_cast<uint32_t*>(&h);
}
__device__ __forceinline__ uint32_t hmax2u(uint32_t a, uint32_t b) {
    __half2 r = __hmax2(*reinterpret_cast<__half2*>(&a), *reinterpret_cast<__half2*>(&b));
    return *reinterpret_cast<uint32_t*>(&r);
}
__device__ __forceinline__ float hmax2_to_f(uint32_t u) {
    float2 f = __half22float2(*reinterpret_cast<__half2*>(&u));
    return fmaxf(f.x, f.y);
}
__device__ __forceinline__ float ex2(float x) {
    float r; asm("ex2.approx.f32 %0, %1;" : "=f"(r) : "f"(x)); return r;
}
__device__ __forceinline__ void cpasync16(uint32_t dst, const void* src) {
    asm volatile("cp.async.cg.shared.global [%0], [%1], 16;" :: "r"(dst), "l"(src) : "memory");
}
#define CP_COMMIT() asm volatile("cp.async.commit_group;" ::: "memory")
#define CP_WAIT0()  asm volatile("cp.async.wait_group 0;" ::: "memory")

// ---- pre-pass: K -> fp16, V -> V^T fp16; also zero the amax tail ----
__global__ __launch_bounds__(256) void prep_kernel(const float* __restrict__ k,
                                                   const float* __restrict__ v,
                                                   float* __restrict__ tail) {
    __shared__ float vs[64][65];
    const int n0 = blockIdx.x * 64;
    const int bh = blockIdx.y;
    const int t = threadIdx.x;
    if (blockIdx.x == 0 && blockIdx.y == 0 && t == 0) { tail[0] = 0.0f; tail[1] = 0.0f; }
    const size_t base = (size_t)bh * SEQ * HD;

    for (int i = t; i < 64 * 16; i += 256) {
        int r = i >> 4, c = (i & 15) * 4;
        size_t eo = base + (size_t)(n0 + r) * HD + c;
        float4 kk = *(const float4*)(k + eo);
        *(uint2*)((uint16_t*)g_khi + eo) =
            make_uint2(packhf(kk.x, kk.y), packhf(kk.z, kk.w));
        float4 vv = *(const float4*)(v + eo);
        vs[r][c] = vv.x; vs[r][c + 1] = vv.y; vs[r][c + 2] = vv.z; vs[r][c + 3] = vv.w;
    }
    __syncthreads();
    const int d = t >> 2;
    const int nn0 = (t & 3) * 16;
    const size_t vbase = ((size_t)bh * HD + d) * SEQ + n0;
    #pragma unroll
    for (int nb = 0; nb < 4; nb++) {
        int n = nn0 + nb * 4;
        *(uint2*)((uint16_t*)g_vthi + vbase + n) =
            make_uint2(packhf(vs[n][d], vs[n + 1][d]), packhf(vs[n + 2][d], vs[n + 3][d]));
    }
}

// async-load one 64-row K/V^T tile (fp16, pre-converted) into a smem stage
__device__ __forceinline__ void issue_tile(uint32_t stg, int bh, int n0, int t) {
    const char* skhi = (const char*)g_khi + ((size_t)bh * SEQ + n0) * HD * 2;
    const char* svhi = (const char*)g_vthi + ((size_t)bh * HD * SEQ + n0) * 2;
    #pragma unroll
    for (int j = 0; j < 2; j++) {
        int rid = (j << 8) + t;            // 0..511 chunks per region
        int r = rid >> 3, c16 = rid & 7;
        cpasync16(stg + r * RB + c16 * 16, skhi + rid * 16);               // K rows 128B
        cpasync16(stg + 9216 + r * RB + c16 * 16,
                  svhi + (size_t)r * (SEQ * 2) + c16 * 16);                // V^T stride 4KB
    }
}

__global__ __launch_bounds__(NTHR, 3) void fa_mma_kernel(
    const float* __restrict__ q,
    const float* __restrict__ dsq, const float* __restrict__ dsk, const float* __restrict__ dsv,
    const float* __restrict__ qss, const float* __restrict__ qso, const float* __restrict__ dss,
    float* __restrict__ out, float* __restrict__ amax_tail)
{
    extern __shared__ char smem[];
    const uint32_t sb = smem_u32(smem);
    float* redf = (float*)(smem + RED_OFF);

    const int t = threadIdx.x, w = t >> 5, lane = t & 31;
    const int g = lane >> 2, tig = lane & 3;
    const int subm = lane >> 3;
    const int a_r = (lane & 7) + ((subm & 1) << 3);
    const int a_c = ((subm >> 1) << 3);
    const int b_r = (lane & 7) + ((subm >> 1) << 3);
    const int b_c = ((subm & 1) << 3);

    const int qt = (gridDim.x - 1) - blockIdx.x;          // heavy tiles first
    const int bh = blockIdx.y;
    const size_t base = (size_t)bh * SEQ * HD;
    const int q0 = qt * BM;

    const float qk_scale = dsq[0] * dsk[0] * 0.125f * LOG2E;   // ex2 domain
    const float pv_scale = qss[0] * dss[0] * dsv[0];
    const float o_scale  = qso[0];

    // prefetch tile 0 first, then convert Q
    issue_tile(sb + STG_OFF, bh, 0, t);
    CP_COMMIT();

    for (int i = t; i < BM * (HD / 4); i += NTHR) {
        int r = i >> 4, c = (i & 15) * 4;
        float4 val = *(const float4*)(q + base + (size_t)(q0 + r) * HD + c);
        val.x *= qk_scale; val.y *= qk_scale; val.z *= qk_scale; val.w *= qk_scale;
        *(uint2*)(smem + QHI_OFF + r * RB + c * 2) =
            make_uint2(packhf(val.x, val.y), packhf(val.z, val.w));
    }

    float o_acc[8][4];
    #pragma unroll
    for (int nb = 0; nb < 8; nb++)
        #pragma unroll
        for (int j = 0; j < 4; j++) o_acc[nb][j] = 0.0f;
    float l0 = 0.0f, l1 = 0.0f;                 // per-thread partial row sums (f32)
    uint32_t hm0 = 0u, hm1 = 0u;                // running fp16x2 max p per row

    const int row_w = q0 + w * 16;
    const int row_hi = row_w + 15;
    const int n_tiles = 2 * qt + 2;

    for (int kt = 0; kt < n_tiles; kt++) {
        const int n0 = kt * BN;
        CP_WAIT0();
        __syncthreads();
        if (kt + 1 < n_tiles) {
            issue_tile(sb + STG_OFF + ((kt + 1) & 1) * STG_SZ, bh, n0 + BN, t);
            CP_COMMIT();
        }
        const uint32_t stg = sb + STG_OFF + (kt & 1) * STG_SZ;

        if (n0 > row_hi) continue;

        // ---- S = Q K^T : single-pass fp16 ----
        float s[8][4];
        #pragma unroll
        for (int nb = 0; nb < 8; nb++)
            #pragma unroll
            for (int j = 0; j < 4; j++) s[nb][j] = 0.0f;

        #pragma unroll
        for (int kb = 0; kb < 4; kb++) {
            uint32_t ah[4], b[4];
            ldsm4(ah, sb + QHI_OFF +
                  (uint32_t)((w * 16 + a_r) * RB + (kb * 16 + a_c) * 2));
            #pragma unroll
            for (int np = 0; np < 4; np++) {
                ldsm4(b, stg + (uint32_t)((np * 16 + b_r) * RB + (kb * 16 + b_c) * 2));
                mma16816(s[2 * np],     ah, b[0], b[1]);
                mma16816(s[2 * np + 1], ah, b[2], b[3]);
            }
        }

        // ---- causal mask ----
        if (n0 + BN - 1 > row_w) {
            const int r0g = row_w + g, r1g = r0g + 8;
            #pragma unroll
            for (int nb = 0; nb < 8; nb++) {
                const int c0 = n0 + nb * 8 + tig * 2;
                if (c0 > r0g)     s[nb][0] = -1e30f;
                if (c0 + 1 > r0g) s[nb][1] = -1e30f;
                if (c0 > r1g)     s[nb][2] = -1e30f;
                if (c0 + 1 > r1g) s[nb][3] = -1e30f;
            }
        }

        // ---- p = 2^s, accumulate l (f32), pack, track fp16 max ----
        uint32_t ph[16];
        #pragma unroll
        for (int nb = 0; nb < 8; nb++) {
            float p0 = ex2(s[nb][0]);
            float p1 = ex2(s[nb][1]);
            float p2 = ex2(s[nb][2]);
            float p3 = ex2(s[nb][3]);
            l0 += p0 + p1;
            l1 += p2 + p3;
            ph[nb * 2]     = packhf(p0, p1);
            ph[nb * 2 + 1] = packhf(p2, p3);
            hm0 = hmax2u(hm0, ph[nb * 2]);
            hm1 = hmax2u(hm1, ph[nb * 2 + 1]);
        }

        // ---- O += P V : single-pass fp16 ----
        #pragma unroll
        for (int kb = 0; kb < 4; kb++) {
            const uint32_t* ap = ph + kb * 4;
            uint32_t b[4];
            #pragma unroll
            for (int np = 0; np < 4; np++) {
                ldsm4(b, stg + 9216 +
                      (uint32_t)((np * 16 + b_r) * RB + (kb * 16 + b_c) * 2));
                mma16816(o_acc[2 * np],     ap, b[0], b[1]);
                mma16816(o_acc[2 * np + 1], ap, b[2], b[3]);
            }
        }
    }

    // ---- epilogue: quad-reduce l across the 4 column lanes, scale, store ----
    l0 += __shfl_xor_sync(0xffffffffu, l0, 1);
    l0 += __shfl_xor_sync(0xffffffffu, l0, 2);
    l1 += __shfl_xor_sync(0xffffffffu, l1, 1);
    l1 += __shfl_xor_sync(0xffffffffu, l1, 2);
    const float il0 = 1.0f / l0, il1 = 1.0f / l1;

    float mx0 = hmax2_to_f(hm0), mx1 = hmax2_to_f(hm1);
    float r0 = fmaxf(mx0, __shfl_xor_sync(0xffffffffu, mx0, 1));
    r0 = fmaxf(r0, __shfl_xor_sync(0xffffffffu, r0, 2));
    float r1 = fmaxf(mx1, __shfl_xor_sync(0xffffffffu, mx1, 1));
    r1 = fmaxf(r1, __shfl_xor_sync(0xffffffffu, r1, 2));
    float amax_s_loc = fmaxf(r0 * il0, r1 * il1);

    float amax_o_loc = 0.0f;
    const int r0g = row_w + g, r1g = r0g + 8;
    #pragma unroll
    for (int nb = 0; nb < 8; nb++) {
        float v0 = o_acc[nb][0] * il0 * pv_scale;
        float v1 = o_acc[nb][1] * il0 * pv_scale;
        float v2 = o_acc[nb][2] * il1 * pv_scale;
        float v3 = o_acc[nb][3] * il1 * pv_scale;
        amax_o_loc = fmaxf(amax_o_loc, fmaxf(fmaxf(fabsf(v0), fabsf(v1)),
                                             fmaxf(fabsf(v2), fabsf(v3))));
        const int c = nb * 8 + tig * 2;
        *(float2*)(out + base + (size_t)r0g * HD + c) = make_float2(v0 * o_scale, v1 * o_scale);
        *(float2*)(out + base + (size_t)r1g * HD + c) = make_float2(v2 * o_scale, v3 * o_scale);
    }

    #pragma unroll
    for (int msk = 16; msk >= 1; msk >>= 1) {
        amax_s_loc = fmaxf(amax_s_loc, __shfl_xor_sync(0xffffffffu, amax_s_loc, msk));
        amax_o_loc = fmaxf(amax_o_loc, __shfl_xor_sync(0xffffffffu, amax_o_loc, msk));
    }
    if (lane == 0) { redf[w] = amax_s_loc; redf[8 + w] = amax_o_loc; }
    __syncthreads();
    if (t == 0) {
        float as = redf[0], ao = redf[8];
        #pragma unroll
        for (int i = 1; i < 8; i++) { as = fmaxf(as, redf[i]); ao = fmaxf(ao, redf[8 + i]); }
        atomic_max_pos(&amax_tail[0], as);
        atomic_max_pos(&amax_tail[1], ao);
    }
}

extern "C" void kernel_launch(void* const* d_in, const int* in_sizes, int n_in,
                              void* d_out, int out_size) {
    const float* q   = (const float*)d_in[0];
    const float* k   = (const float*)d_in[1];
    const float* v   = (const float*)d_in[2];
    const float* dsq = (const float*)d_in[3];
    const float* dsk = (const float*)d_in[4];
    const float* dsv = (const float*)d_in[5];
    const float* qss = (const float*)d_in[6];
    const float* qso = (const float*)d_in[7];
    const float* dss = (const float*)d_in[8];
    float* out = (float*)d_out;
    float* tail = out + (out_size - 2);

    cudaFuncSetAttribute(fa_mma_kernel,
                         cudaFuncAttributeMaxDynamicSharedMemorySize, SMEM_TOTAL);

    prep_kernel<<<dim3(SEQ / 64, BH), 256>>>(k, v, tail);

    dim3 grid(SEQ / BM, BH);                 // (16, 32)
    fa_mma_kernel<<<grid, NTHR, SMEM_TOTAL>>>(q, dsq, dsk, dsv, qss, qso, dss,
                                              out, tail);
}